// round 2
// baseline (speedup 1.0000x reference)
#include <cuda_runtime.h>
#include <math.h>

#define B_N   8
#define C_IN  128
#define HWD   128
#define PLANE (HWD*HWD)

// ---- scratch (static __device__, no runtime allocation) -------------------
__device__ float d_pools[B_N * C_IN * 52];          // pooled knot values per (b,c)
__device__ float d_Q    [B_N * 8 * 96 * 16];        // per (b,g): 96 gi-rows x knots (stride 16, bih folded)
__device__ float d_Wall [8 * 128 * 16];             // per g: rows 0..95 = Whh@Wc, 96..127 = Wc

__device__ __forceinline__ int bin_s(int i, int o) { return (i * HWD) / o; }
__device__ __forceinline__ int bin_e(int i, int o) { return ((i + 1) * HWD + o - 1) / o; }

__device__ __forceinline__ float sigf(float v) {
    return __fdividef(1.0f, 1.0f + __expf(-v));
}
__device__ __forceinline__ float tanh_fast(float v) {
    v = fminf(fmaxf(v, -15.0f), 15.0f);
    float e = __expf(-2.0f * v);
    return __fdividef(1.0f - e, 1.0f + e);
}

// ---------------------------------------------------------------------------
// K1: adaptive avg-pool of x to all 4 target grids. One block per (b,c) plane.
//   outputs per (b,c), 52 knots: [0,11) br0(1,11) | [11,22) br1(11,1)
//                                [22,37) br2(3,5) | [37,52) br3(5,3)
// ---------------------------------------------------------------------------
__global__ __launch_bounds__(128) void k_pool(const float* __restrict__ x,
                                              float* __restrict__ pools)
{
    __shared__ float scol[20 * HWD];   // h-binned column sums: [o1 | o11 x11 | o3 x3 | o5 x5]
    const int bc = blockIdx.x;
    const int t  = threadIdx.x;
    const float* pl = x + (size_t)bc * PLANE;

    {   // o_h = 1 (full column) — 4 partial accumulators for ILP
        float a0 = 0.f, a1 = 0.f, a2 = 0.f, a3 = 0.f;
        #pragma unroll 8
        for (int h = 0; h < HWD; h += 4) {
            a0 += pl[(h + 0) * HWD + t];
            a1 += pl[(h + 1) * HWD + t];
            a2 += pl[(h + 2) * HWD + t];
            a3 += pl[(h + 3) * HWD + t];
        }
        scol[t] = (a0 + a1) + (a2 + a3);
    }
    #pragma unroll
    for (int i = 0; i < 11; ++i) {
        const int s = bin_s(i, 11), e = bin_e(i, 11);
        float a = 0.f;
        #pragma unroll
        for (int h = s; h < e; ++h) a += pl[h * HWD + t];
        scol[(1 + i) * HWD + t] = a;
    }
    #pragma unroll
    for (int i = 0; i < 3; ++i) {
        const int s = bin_s(i, 3), e = bin_e(i, 3);
        float a = 0.f;
        #pragma unroll
        for (int h = s; h < e; ++h) a += pl[h * HWD + t];
        scol[(12 + i) * HWD + t] = a;
    }
    #pragma unroll
    for (int i = 0; i < 5; ++i) {
        const int s = bin_s(i, 5), e = bin_e(i, 5);
        float a = 0.f;
        #pragma unroll
        for (int h = s; h < e; ++h) a += pl[h * HWD + t];
        scol[(15 + i) * HWD + t] = a;
    }
    __syncthreads();

    if (t < 52) {
        int hrow, hcnt, ws, we;
        if (t < 11)      { hrow = 0;                    hcnt = HWD;
                           ws = bin_s(t, 11); we = bin_e(t, 11); }
        else if (t < 22) { int i = t - 11; hrow = 1 + i;
                           hcnt = bin_e(i, 11) - bin_s(i, 11); ws = 0; we = HWD; }
        else if (t < 37) { int l = t - 22, y = l / 5, xx = l % 5;
                           hrow = 12 + y; hcnt = bin_e(y, 3) - bin_s(y, 3);
                           ws = bin_s(xx, 5); we = bin_e(xx, 5); }
        else             { int l = t - 37, y = l / 3, xx = l % 3;
                           hrow = 15 + y; hcnt = bin_e(y, 5) - bin_s(y, 5);
                           ws = bin_s(xx, 3); we = bin_e(xx, 3); }
        float a = 0.f;
        for (int w = ws; w < we; ++w) a += scol[hrow * HWD + w];
        pools[bc * 52 + t] = a / (float)(hcnt * (we - ws));
    }
}

// ---------------------------------------------------------------------------
// K2: per (b,g) knot table Q: branch linear -> merge -> Wih (+bih folded).
//   group g uses branch k=g>>1, branch channels [64*(g&1), +64)
// ---------------------------------------------------------------------------
__global__ __launch_bounds__(128) void k_Q(
    const float* __restrict__ W0, const float* __restrict__ b0,
    const float* __restrict__ W1, const float* __restrict__ b1,
    const float* __restrict__ W2, const float* __restrict__ b2,
    const float* __restrict__ W3, const float* __restrict__ b3,
    const float* __restrict__ Wm,
    const float* __restrict__ Wih, const float* __restrict__ bih)
{
    const int b = blockIdx.x >> 3, g = blockIdx.x & 7;
    const int k = g >> 1, half = g & 1;
    int S, off; const float* Wl; const float* bl;
    switch (k) {
        case 0:  S = 11; off = 0;  Wl = W0; bl = b0; break;
        case 1:  S = 11; off = 11; Wl = W1; bl = b1; break;
        case 2:  S = 15; off = 22; Wl = W2; bl = b2; break;
        default: S = 15; off = 37; Wl = W3; bl = b3; break;
    }
    __shared__ float sWl[225], sbl[15], spool[64 * 16], sp2[64 * 16],
                     sbg[32 * 16], sWih[96 * 32];
    const int tid = threadIdx.x;

    for (int i = tid; i < S * S;   i += 128) sWl[i]  = Wl[i];
    for (int i = tid; i < S;       i += 128) sbl[i]  = bl[i];
    for (int i = tid; i < 96 * 32; i += 128) sWih[i] = Wih[g * 3072 + i];
    for (int i = tid; i < 64 * S;  i += 128) {
        int cc = i / S, t = i - cc * S;
        spool[cc * 16 + t] = d_pools[(b * C_IN + 64 * half + cc) * 52 + off + t];
    }
    __syncthreads();
    for (int i = tid; i < 64 * S; i += 128) {       // per-channel linear on pooled grid
        int cc = i / S, jj = i - cc * S;
        float a = sbl[jj];
        for (int t = 0; t < S; ++t) a += sWl[jj * S + t] * spool[cc * 16 + t];
        sp2[cc * 16 + jj] = a;
    }
    __syncthreads();
    for (int i = tid; i < 32 * S; i += 128) {       // merge: 4 branch-ch -> m
        int m = i / S, t = i - m * S;
        const float* wp = Wm + (size_t)(16 * g + (m >> 1)) * 8 + (m & 1) * 4;
        int cb = (m >> 1) * 4;
        sbg[m * 16 + t] = wp[0] * sp2[(cb + 0) * 16 + t] + wp[1] * sp2[(cb + 1) * 16 + t]
                        + wp[2] * sp2[(cb + 2) * 16 + t] + wp[3] * sp2[(cb + 3) * 16 + t];
    }
    __syncthreads();
    for (int i = tid; i < 96 * S; i += 128) {       // Wih, fold bih
        int r = i / S, t = i - r * S;
        float a = bih[g * 96 + r];
        #pragma unroll 8
        for (int m = 0; m < 32; ++m) a += sWih[r * 32 + m] * sbg[m * 16 + t];
        d_Q[((size_t)(b * 8 + g) * 96 + r) * 16 + t] = a;
    }
}

// ---------------------------------------------------------------------------
// K3: Wall[g] = [ Whh[g] @ W_center[g] (96x16) ; W_center[g] (32x16) ]
// ---------------------------------------------------------------------------
__global__ __launch_bounds__(128) void k_wcomp(const float* __restrict__ Whh,
                                               const float* __restrict__ Wc)
{
    __shared__ float sWhh[96 * 32], sWc[32 * 16];
    const int g = blockIdx.x, t = threadIdx.x;
    for (int i = t; i < 3072; i += 128) sWhh[i] = Whh[g * 3072 + i];
    for (int i = t; i < 512;  i += 128) sWc[i]  = Wc[g * 512 + i];
    __syncthreads();
    for (int e = t; e < 96 * 16; e += 128) {
        int r = e >> 4, i = e & 15;
        float a = 0.f;
        #pragma unroll 8
        for (int hh = 0; hh < 32; ++hh) a += sWhh[r * 32 + hh] * sWc[hh * 16 + i];
        d_Wall[g * 2048 + r * 16 + i] = a;
    }
    for (int e = t; e < 512; e += 128) d_Wall[g * 2048 + 1536 + e] = sWc[e];
}

// ---------------------------------------------------------------------------
// K4: main fused kernel. Block = one (b, h) image row, thread = w.
// smem floats: sW 16384 | sQ01 2112 | gic 192 | sR45 960 | sR67 576 | sBhh 768
// ---------------------------------------------------------------------------
#define SMEM_FLOATS (16384 + 2112 + 192 + 960 + 576 + 768)

__global__ __launch_bounds__(128, 2) void k_main(const float* __restrict__ x,
                                                 const float* __restrict__ bhh,
                                                 float* __restrict__ out)
{
    extern __shared__ float sm[];
    float* sW   = sm;                  // 8 x 128 x 16
    float* sQ01 = sW + 16384;          // 2 x 96 x 11
    float* gic  = sQ01 + 2112;         // 2 x 96
    float* sR45 = gic + 192;           // 2 x 96 x 5
    float* sR67 = sR45 + 960;          // 2 x 96 x 3
    float* sBhh = sR67 + 576;          // 8 x 96

    const int h = blockIdx.x, b = blockIdx.y, t = threadIdx.x;

    {   // stage weights (vectorized) + bhh
        const float4* ws = (const float4*)d_Wall;
        float4* wd = (float4*)sW;
        for (int i = t; i < 4096; i += 128) wd[i] = ws[i];
        for (int i = t; i < 768;  i += 128) sBhh[i] = bhh[i];
    }
    const float* Qb = d_Q + (size_t)b * (8 * 96 * 16);
    for (int i = t; i < 2 * 96 * 11; i += 128) {         // groups 0,1: raw knots
        int g = i / 1056, rem = i - g * 1056, r = rem / 11, tt = rem - r * 11;
        sQ01[i] = Qb[(g * 96 + r) * 16 + tt];
    }
    {   // groups 2,3: h-interp of 11 knots -> per-row constant
        float fh = h * (10.0f / 127.0f);
        int i0 = min((int)fh, 9); float th = fh - (float)i0;
        for (int i = t; i < 2 * 96; i += 128) {
            int g = 2 + i / 96, r = i % 96;
            const float* q = Qb + (g * 96 + r) * 16;
            gic[i] = q[i0] + th * (q[i0 + 1] - q[i0]);
        }
    }
    {   // groups 4,5: (3,5) grid, h-interp -> 5 w-knots
        float fh = h * (2.0f / 127.0f);
        int i0 = min((int)fh, 1); float th = fh - (float)i0;
        for (int i = t; i < 2 * 96 * 5; i += 128) {
            int g = 4 + i / 480, rem = i % 480, r = rem / 5, xx = rem % 5;
            const float* q = Qb + (g * 96 + r) * 16;
            float v0 = q[i0 * 5 + xx], v1 = q[i0 * 5 + 5 + xx];
            sR45[i] = v0 + th * (v1 - v0);
        }
    }
    {   // groups 6,7: (5,3) grid, h-interp -> 3 w-knots
        float fh = h * (4.0f / 127.0f);
        int i0 = min((int)fh, 3); float th = fh - (float)i0;
        for (int i = t; i < 2 * 96 * 3; i += 128) {
            int g = 6 + i / 288, rem = i % 288, r = rem / 3, xx = rem % 3;
            const float* q = Qb + (g * 96 + r) * 16;
            float v0 = q[i0 * 3 + xx], v1 = q[i0 * 3 + 3 + xx];
            sR67[i] = v0 + th * (v1 - v0);
        }
    }
    __syncthreads();

    // per-thread w-interp coords
    float f11 = t * (10.0f / 127.0f); int i11 = min((int)f11, 9); float t11 = f11 - (float)i11;
    float f5  = t * (4.0f  / 127.0f); int i5  = min((int)f5,  3); float t5  = f5  - (float)i5;
    float f3  = t * (2.0f  / 127.0f); int i3  = min((int)f3,  1); float t3  = f3  - (float)i3;

    const float* xp = x   + ((size_t)b * C_IN) * PLANE + h * HWD + t;
    float*       op = out + ((size_t)b * 256 ) * PLANE + h * HWD + t;

    #pragma unroll
    for (int g = 0; g < 8; ++g) {
        float t16[16];
        #pragma unroll
        for (int i = 0; i < 16; ++i) t16[i] = xp[(size_t)(16 * g + i) * PLANE];

        const float* W  = sW + g * 2048;
        const float* bh = sBhh + g * 96;
        const float* giB; int giStride, giD; float giT;
        if (g < 2)      { giB = sQ01 + g * 1056 + i11;       giStride = 11; giT = t11; giD = 1; }
        else if (g < 4) { giB = gic + (g - 2) * 96;          giStride = 1;  giT = 0.f; giD = 0; }
        else if (g < 6) { giB = sR45 + (g - 4) * 480 + i5;   giStride = 5;  giT = t5;  giD = 1; }
        else            { giB = sR67 + (g - 6) * 288 + i3;   giStride = 3;  giT = t3;  giD = 1; }

        #pragma unroll 2
        for (int j = 0; j < 32; ++j) {
            float ar = 0.f, az = 0.f, an = 0.f, ac = 0.f;
            #pragma unroll
            for (int i = 0; i < 16; ++i) {
                float v = t16[i];
                ar += W[ j        * 16 + i] * v;
                az += W[(32 + j)  * 16 + i] * v;
                an += W[(64 + j)  * 16 + i] * v;
                ac += W[(96 + j)  * 16 + i] * v;
            }
            ar += bh[j]; az += bh[32 + j]; an += bh[64 + j];
            float gr0 = giB[ j       * giStride], gr1 = giB[ j       * giStride + giD];
            float gz0 = giB[(32 + j) * giStride], gz1 = giB[(32 + j) * giStride + giD];
            float gn0 = giB[(64 + j) * giStride], gn1 = giB[(64 + j) * giStride + giD];
            float gir = gr0 + giT * (gr1 - gr0);
            float giz = gz0 + giT * (gz1 - gz0);
            float gin = gn0 + giT * (gn1 - gn0);
            float r = sigf(gir + ar);
            float z = sigf(giz + az);
            float n = tanh_fast(gin + r * an);
            op[(size_t)(j * 8 + g) * PLANE] = n + z * (ac - n);
        }
    }
}

// ---------------------------------------------------------------------------
extern "C" void kernel_launch(void* const* d_in, const int* in_sizes, int n_in,
                              void* d_out, int out_size)
{
    const float* x   = (const float*)d_in[0];
    const float* Wc  = (const float*)d_in[1];
    const float* W0  = (const float*)d_in[2];
    const float* b0  = (const float*)d_in[3];
    const float* W1  = (const float*)d_in[4];
    const float* b1  = (const float*)d_in[5];
    const float* W2  = (const float*)d_in[6];
    const float* b2  = (const float*)d_in[7];
    const float* W3  = (const float*)d_in[8];
    const float* b3  = (const float*)d_in[9];
    const float* Wm  = (const float*)d_in[10];
    const float* Wih = (const float*)d_in[11];
    const float* Whh = (const float*)d_in[12];
    const float* bih = (const float*)d_in[13];
    const float* bhh = (const float*)d_in[14];
    float* out = (float*)d_out;

    float* pools = nullptr;
    cudaGetSymbolAddress((void**)&pools, d_pools);

    static bool attr_set = false;
    if (!attr_set) {
        cudaFuncSetAttribute(k_main, cudaFuncAttributeMaxDynamicSharedMemorySize,
                             SMEM_FLOATS * (int)sizeof(float));
        attr_set = true;
    }

    k_pool<<<B_N * C_IN, 128>>>(x, pools);
    k_wcomp<<<8, 128>>>(Whh, Wc);
    k_Q<<<B_N * 8, 128>>>(W0, b0, W1, b1, W2, b2, W3, b3, Wm, Wih, bih);
    k_main<<<dim3(HWD, B_N), 128, SMEM_FLOATS * sizeof(float)>>>(x, bhh, out);
}

// round 10
// speedup vs baseline: 1.5203x; 1.5203x over previous
#include <cuda_runtime.h>
#include <math.h>

#define B_N   8
#define C_IN  128
#define HWD   128
#define PLANE (HWD*HWD)

// ---- scratch (static __device__, no runtime allocation) -------------------
__device__ float d_pools[B_N * C_IN * 52];          // pooled knot values per (b,c)
__device__ float d_Q    [B_N * 8 * 96 * 16];        // per (b,g): 96 gi-rows x knots (stride 16, bih folded)
// d_Wall layout per g (2048 floats):
//   [0,1024):    (r,z) weight pairs:  idx (j*16+i)*2 -> {Wcomp[j][i], Wcomp[32+j][i]}
//   [1024,2048): (n,c) weight pairs:  idx (j*16+i)*2 -> {Wcomp[64+j][i], Wc[j][i]}
__device__ float d_Wall [8 * 2048];

__device__ __forceinline__ int bin_s(int i, int o) { return (i * HWD) / o; }
__device__ __forceinline__ int bin_e(int i, int o) { return ((i + 1) * HWD + o - 1) / o; }

__device__ __forceinline__ float sigf(float v) {
    return __fdividef(1.0f, 1.0f + __expf(-v));
}
__device__ __forceinline__ float tanh_fast(float v) {
    v = fminf(fmaxf(v, -15.0f), 15.0f);
    float e = __expf(-2.0f * v);
    return __fdividef(1.0f - e, 1.0f + e);
}

// ---- packed f32x2 helpers (sm_103a: fma.rn.f32x2 is PTX-only) -------------
__device__ __forceinline__ unsigned long long pk2(float lo, float hi) {
    unsigned long long r;
    asm("mov.b64 %0, {%1, %2};" : "=l"(r) : "f"(lo), "f"(hi));
    return r;
}
__device__ __forceinline__ void upk2(unsigned long long v, float& lo, float& hi) {
    asm("mov.b64 {%0, %1}, %2;" : "=f"(lo), "=f"(hi) : "l"(v));
}
__device__ __forceinline__ unsigned long long fma2(unsigned long long a,
                                                   unsigned long long b,
                                                   unsigned long long c) {
    unsigned long long d;
    asm("fma.rn.f32x2 %0, %1, %2, %3;" : "=l"(d) : "l"(a), "l"(b), "l"(c));
    return d;
}
__device__ __forceinline__ unsigned long long add2(unsigned long long a,
                                                   unsigned long long b) {
    unsigned long long d;
    asm("add.rn.f32x2 %0, %1, %2;" : "=l"(d) : "l"(a), "l"(b));
    return d;
}

// ---------------------------------------------------------------------------
// K1: adaptive avg-pool of x to all 4 target grids, single pass over plane.
//   outputs per (b,c), 52 knots: [0,11) br0(1,11) | [11,22) br1(11,1)
//                                [22,37) br2(3,5) | [37,52) br3(5,3)
// ---------------------------------------------------------------------------
__global__ __launch_bounds__(128) void k_pool(const float* __restrict__ x,
                                              float* __restrict__ pools)
{
    __shared__ float scol[20 * HWD];   // [o1 | o11 x11 | o3 x3 | o5 x5]
    const int bc = blockIdx.x;
    const int t  = threadIdx.x;
    const float* pl = x + (size_t)bc * PLANE;

    float a1 = 0.f;
    float a11[11], a3[3], a5[5];
    #pragma unroll
    for (int i = 0; i < 11; ++i) a11[i] = 0.f;
    #pragma unroll
    for (int i = 0; i < 3; ++i) a3[i] = 0.f;
    #pragma unroll
    for (int i = 0; i < 5; ++i) a5[i] = 0.f;

    #pragma unroll
    for (int h = 0; h < HWD; ++h) {
        float v = pl[h * HWD + t];
        a1 += v;
        #pragma unroll
        for (int i = 0; i < 11; ++i)
            if (h >= bin_s(i, 11) && h < bin_e(i, 11)) a11[i] += v;
        #pragma unroll
        for (int i = 0; i < 3; ++i)
            if (h >= bin_s(i, 3) && h < bin_e(i, 3)) a3[i] += v;
        #pragma unroll
        for (int i = 0; i < 5; ++i)
            if (h >= bin_s(i, 5) && h < bin_e(i, 5)) a5[i] += v;
    }
    scol[t] = a1;
    #pragma unroll
    for (int i = 0; i < 11; ++i) scol[(1 + i) * HWD + t] = a11[i];
    #pragma unroll
    for (int i = 0; i < 3; ++i)  scol[(12 + i) * HWD + t] = a3[i];
    #pragma unroll
    for (int i = 0; i < 5; ++i)  scol[(15 + i) * HWD + t] = a5[i];
    __syncthreads();

    if (t < 52) {
        int hrow, hcnt, ws, we;
        if (t < 11)      { hrow = 0;                    hcnt = HWD;
                           ws = bin_s(t, 11); we = bin_e(t, 11); }
        else if (t < 22) { int i = t - 11; hrow = 1 + i;
                           hcnt = bin_e(i, 11) - bin_s(i, 11); ws = 0; we = HWD; }
        else if (t < 37) { int l = t - 22, y = l / 5, xx = l % 5;
                           hrow = 12 + y; hcnt = bin_e(y, 3) - bin_s(y, 3);
                           ws = bin_s(xx, 5); we = bin_e(xx, 5); }
        else             { int l = t - 37, y = l / 3, xx = l % 3;
                           hrow = 15 + y; hcnt = bin_e(y, 5) - bin_s(y, 5);
                           ws = bin_s(xx, 3); we = bin_e(xx, 3); }
        float a = 0.f;
        for (int w = ws; w < we; ++w) a += scol[hrow * HWD + w];
        pools[bc * 52 + t] = a / (float)(hcnt * (we - ws));
    }
}

// ---------------------------------------------------------------------------
// K2: per (b,g) knot table Q: branch linear -> merge -> Wih (+bih folded).
//   group g uses branch k=g>>1, branch channels [64*(g&1), +64)
// ---------------------------------------------------------------------------
__global__ __launch_bounds__(128) void k_Q(
    const float* __restrict__ W0, const float* __restrict__ b0,
    const float* __restrict__ W1, const float* __restrict__ b1,
    const float* __restrict__ W2, const float* __restrict__ b2,
    const float* __restrict__ W3, const float* __restrict__ b3,
    const float* __restrict__ Wm,
    const float* __restrict__ Wih, const float* __restrict__ bih)
{
    const int b = blockIdx.x >> 3, g = blockIdx.x & 7;
    const int k = g >> 1, half = g & 1;
    int S, off; const float* Wl; const float* bl;
    switch (k) {
        case 0:  S = 11; off = 0;  Wl = W0; bl = b0; break;
        case 1:  S = 11; off = 11; Wl = W1; bl = b1; break;
        case 2:  S = 15; off = 22; Wl = W2; bl = b2; break;
        default: S = 15; off = 37; Wl = W3; bl = b3; break;
    }
    __shared__ float sWl[225], sbl[15], spool[64 * 16], sp2[64 * 16],
                     sbg[32 * 16], sWih[96 * 32];
    const int tid = threadIdx.x;

    for (int i = tid; i < S * S;   i += 128) sWl[i]  = Wl[i];
    for (int i = tid; i < S;       i += 128) sbl[i]  = bl[i];
    for (int i = tid; i < 96 * 32; i += 128) sWih[i] = Wih[g * 3072 + i];
    for (int i = tid; i < 64 * S;  i += 128) {
        int cc = i / S, t = i - cc * S;
        spool[cc * 16 + t] = d_pools[(b * C_IN + 64 * half + cc) * 52 + off + t];
    }
    __syncthreads();
    for (int i = tid; i < 64 * S; i += 128) {       // per-channel linear on pooled grid
        int cc = i / S, jj = i - cc * S;
        float a = sbl[jj];
        for (int t = 0; t < S; ++t) a += sWl[jj * S + t] * spool[cc * 16 + t];
        sp2[cc * 16 + jj] = a;
    }
    __syncthreads();
    for (int i = tid; i < 32 * S; i += 128) {       // merge: 4 branch-ch -> m
        int m = i / S, t = i - m * S;
        const float* wp = Wm + (size_t)(16 * g + (m >> 1)) * 8 + (m & 1) * 4;
        int cb = (m >> 1) * 4;
        sbg[m * 16 + t] = wp[0] * sp2[(cb + 0) * 16 + t] + wp[1] * sp2[(cb + 1) * 16 + t]
                        + wp[2] * sp2[(cb + 2) * 16 + t] + wp[3] * sp2[(cb + 3) * 16 + t];
    }
    __syncthreads();
    for (int i = tid; i < 96 * S; i += 128) {       // Wih, fold bih
        int r = i / S, t = i - r * S;
        float a = bih[g * 96 + r];
        #pragma unroll 8
        for (int m = 0; m < 32; ++m) a += sWih[r * 32 + m] * sbg[m * 16 + t];
        d_Q[((size_t)(b * 8 + g) * 96 + r) * 16 + t] = a;
    }
}

// ---------------------------------------------------------------------------
// K3: Wcomp = Whh @ Wc (96x16), emit interleaved (r,z)/(n,c) pair layout.
// ---------------------------------------------------------------------------
__global__ __launch_bounds__(128) void k_wcomp(const float* __restrict__ Whh,
                                               const float* __restrict__ Wc)
{
    __shared__ float sWhh[96 * 32], sWc[32 * 16], sComp[96 * 16];
    const int g = blockIdx.x, t = threadIdx.x;
    for (int i = t; i < 3072; i += 128) sWhh[i] = Whh[g * 3072 + i];
    for (int i = t; i < 512;  i += 128) sWc[i]  = Wc[g * 512 + i];
    __syncthreads();
    for (int e = t; e < 96 * 16; e += 128) {
        int r = e >> 4, i = e & 15;
        float a = 0.f;
        #pragma unroll 8
        for (int hh = 0; hh < 32; ++hh) a += sWhh[r * 32 + hh] * sWc[hh * 16 + i];
        sComp[e] = a;
    }
    __syncthreads();
    float* Wd = d_Wall + g * 2048;
    for (int e = t; e < 512; e += 128) {            // e = j*16+i
        int j = e >> 4, i = e & 15;
        Wd[e * 2 + 0]        = sComp[ j        * 16 + i];   // r
        Wd[e * 2 + 1]        = sComp[(32 + j)  * 16 + i];   // z
        Wd[1024 + e * 2 + 0] = sComp[(64 + j)  * 16 + i];   // n
        Wd[1024 + e * 2 + 1] = sWc[j * 16 + i];             // c
    }
}

// ---------------------------------------------------------------------------
// K4: main fused kernel. Block = (2 image rows) x (one GRU group g).
//   grid (64, 8, 8); 256 threads: w = t&127, row = t>>7. ~13.5 KB static smem.
//   Gate dots computed with fma.rn.f32x2 on (r,z)/(n,c) pairs.
// ---------------------------------------------------------------------------
__global__ __launch_bounds__(256, 3) void k_main(const float* __restrict__ x,
                                                 const float* __restrict__ bhh,
                                                 float* __restrict__ out)
{
    __shared__ __align__(16) float sW[2048];   // interleaved pair layout (see d_Wall)
    __shared__ __align__(8)  float sB0[64];    // (bhh_r[j], bhh_z[j]) pairs
    __shared__ __align__(8)  float sB1[64];    // (bhh_n[j], 0) pairs
    __shared__ float sK[1056];                 // knot table (layout depends on g)

    const int g   = blockIdx.y;
    const int b   = blockIdx.z;
    const int t   = threadIdx.x;
    const int w   = t & 127;
    const int row = t >> 7;
    const int h   = blockIdx.x * 2 + row;

    {   // stage W (float4) + bias pairs
        const float4* ws = (const float4*)(d_Wall + g * 2048);
        float4* wd = (float4*)sW;
        for (int i = t; i < 512; i += 256) wd[i] = ws[i];
        if (t < 32) {
            sB0[2 * t]     = bhh[g * 96 + t];
            sB0[2 * t + 1] = bhh[g * 96 + 32 + t];
            sB1[2 * t]     = bhh[g * 96 + 64 + t];
            sB1[2 * t + 1] = 0.f;
        }
    }
    const float* Qb = d_Q + (size_t)(b * 8 + g) * 96 * 16;
    if (g < 2) {                    // branch (1,11): h-constant, 11 w-knots
        for (int i = t; i < 96 * 11; i += 256) {
            int r = i / 11, tt = i - r * 11;
            sK[i] = Qb[r * 16 + tt];
        }
    } else if (g < 4) {             // branch (11,1): w-constant, h-interp -> [row][r]
        for (int i = t; i < 2 * 96; i += 256) {
            int rr = i / 96, r = i - rr * 96;
            float fh = (float)(blockIdx.x * 2 + rr) * (10.0f / 127.0f);
            int i0 = min((int)fh, 9); float th = fh - (float)i0;
            const float* q = Qb + r * 16;
            sK[i] = q[i0] + th * (q[i0 + 1] - q[i0]);
        }
    } else if (g < 6) {             // (3,5): h-interp -> [row][r][5]
        for (int i = t; i < 2 * 96 * 5; i += 256) {
            int rr = i / 480, rem = i - rr * 480, r = rem / 5, xx = rem - r * 5;
            float fh = (float)(blockIdx.x * 2 + rr) * (2.0f / 127.0f);
            int i0 = min((int)fh, 1); float th = fh - (float)i0;
            const float* q = Qb + r * 16;
            float v0 = q[i0 * 5 + xx], v1 = q[i0 * 5 + 5 + xx];
            sK[i] = v0 + th * (v1 - v0);
        }
    } else {                        // (5,3): h-interp -> [row][r][3]
        for (int i = t; i < 2 * 96 * 3; i += 256) {
            int rr = i / 288, rem = i - rr * 288, r = rem / 3, xx = rem - r * 3;
            float fh = (float)(blockIdx.x * 2 + rr) * (4.0f / 127.0f);
            int i0 = min((int)fh, 3); float th = fh - (float)i0;
            const float* q = Qb + r * 16;
            float v0 = q[i0 * 3 + xx], v1 = q[i0 * 3 + 3 + xx];
            sK[i] = v0 + th * (v1 - v0);
        }
    }
    __syncthreads();

    // per-thread w-interp parameters
    const float* KB; int S, D; float tw;
    if (g < 2) {
        float f = w * (10.0f / 127.0f); int i0 = min((int)f, 9);
        KB = sK + i0; S = 11; tw = f - (float)i0; D = 1;
    } else if (g < 4) {
        KB = sK + row * 96; S = 1; tw = 0.f; D = 0;
    } else if (g < 6) {
        float f = w * (4.0f / 127.0f); int i0 = min((int)f, 3);
        KB = sK + row * 480 + i0; S = 5; tw = f - (float)i0; D = 1;
    } else {
        float f = w * (2.0f / 127.0f); int i0 = min((int)f, 1);
        KB = sK + row * 288 + i0; S = 3; tw = f - (float)i0; D = 1;
    }

    // load this thread's 16 input channels (group g), pack as (v,v)
    const float* xp = x + ((size_t)(b * C_IN + 16 * g)) * PLANE + h * HWD + w;
    unsigned long long vv[16];
    #pragma unroll
    for (int i = 0; i < 16; ++i) {
        float v = xp[(size_t)i * PLANE];
        vv[i] = pk2(v, v);
    }

    float* op = out + ((size_t)b * 256) * PLANE + h * HWD + w;
    const ulonglong2* Wrz = (const ulonglong2*)sW;            // [32][8] pairs-of-pairs
    const ulonglong2* Wnc = (const ulonglong2*)(sW + 1024);
    const unsigned long long* B0 = (const unsigned long long*)sB0;
    const unsigned long long* B1 = (const unsigned long long*)sB1;

    #pragma unroll 4
    for (int j = 0; j < 32; ++j) {
        unsigned long long a0  = B0[j], a0b = 0ull;   // (ar, az), biases folded
        unsigned long long a1  = B1[j], a1b = 0ull;   // (an, ac)
        #pragma unroll
        for (int i2 = 0; i2 < 8; ++i2) {
            ulonglong2 wa = Wrz[j * 8 + i2];
            ulonglong2 wb = Wnc[j * 8 + i2];
            a0  = fma2(wa.x, vv[2 * i2],     a0);
            a0b = fma2(wa.y, vv[2 * i2 + 1], a0b);
            a1  = fma2(wb.x, vv[2 * i2],     a1);
            a1b = fma2(wb.y, vv[2 * i2 + 1], a1b);
        }
        a0 = add2(a0, a0b);
        a1 = add2(a1, a1b);
        float ar, az, an, ac;
        upk2(a0, ar, az);
        upk2(a1, an, ac);

        float gr0 = KB[ j       * S], gr1 = KB[ j       * S + D];
        float gz0 = KB[(32 + j) * S], gz1 = KB[(32 + j) * S + D];
        float gn0 = KB[(64 + j) * S], gn1 = KB[(64 + j) * S + D];
        float gir = gr0 + tw * (gr1 - gr0);
        float giz = gz0 + tw * (gz1 - gz0);
        float gin = gn0 + tw * (gn1 - gn0);
        float r = sigf(gir + ar);
        float z = sigf(giz + az);
        float n = tanh_fast(gin + r * an);
        op[(size_t)(j * 8 + g) * PLANE] = n + z * (ac - n);
    }
}

// ---------------------------------------------------------------------------
extern "C" void kernel_launch(void* const* d_in, const int* in_sizes, int n_in,
                              void* d_out, int out_size)
{
    const float* x   = (const float*)d_in[0];
    const float* Wc  = (const float*)d_in[1];
    const float* W0  = (const float*)d_in[2];
    const float* b0  = (const float*)d_in[3];
    const float* W1  = (const float*)d_in[4];
    const float* b1  = (const float*)d_in[5];
    const float* W2  = (const float*)d_in[6];
    const float* b2  = (const float*)d_in[7];
    const float* W3  = (const float*)d_in[8];
    const float* b3  = (const float*)d_in[9];
    const float* Wm  = (const float*)d_in[10];
    const float* Wih = (const float*)d_in[11];
    const float* Whh = (const float*)d_in[12];
    const float* bih = (const float*)d_in[13];
    const float* bhh = (const float*)d_in[14];
    float* out = (float*)d_out;

    float* pools = nullptr;
    cudaGetSymbolAddress((void**)&pools, d_pools);

    k_pool<<<B_N * C_IN, 128>>>(x, pools);
    k_wcomp<<<8, 128>>>(Whh, Wc);
    k_Q<<<B_N * 8, 128>>>(W0, b0, W1, b1, W2, b2, W3, b3, Wm, Wih, bih);
    k_main<<<dim3(HWD / 2, 8, B_N), 256>>>(x, bhh, out);
}